// round 10
// baseline (speedup 1.0000x reference)
#include <cuda_runtime.h>
#include <cstdint>

#define N_NODES 50000
#define N_EDGES 800000
#define EAUG    (N_EDGES + N_NODES)
#define HID     128
#define NCLS    40

// ---------------- scratch (static device globals; no runtime alloc) --------
__device__ float  d_h0 [N_NODES * HID];
__device__ float  d_x1 [N_NODES * HID];
__device__ float  d_tmp[N_NODES * HID];
__device__ float  d_G  [(size_t)N_NODES * 256];   // [xg | xself]
__device__ float  d_AGG[(size_t)N_NODES * 256];   // [g0*sc | g1*sd]
__device__ float  d_g2 [N_NODES];
__device__ float2 d_PQ [N_NODES];
__device__ float4 d_T  [N_NODES];                 // gate-self logit terms
__device__ float  d_V  [768];                     // fused gate vectors
__device__ float2 d_s  [EAUG];                    // {exp(s), exp(1-s)}
__device__ float  d_Z  [2 * N_NODES];
__device__ float  d_stats[2 * HID];
__device__ int    d_off [N_NODES + 1];
__device__ int    d_cur [N_NODES];
__device__ int    d_cnt [N_NODES];
__device__ int    d_eid [EAUG];

// ============================================================================
// bf16x3 split helpers (shared by both tensor-core GEMMs)
// ============================================================================
__device__ __forceinline__ uint32_t prmt_hi(uint32_t a, uint32_t b) {
    uint32_t d;
    asm("prmt.b32 %0, %1, %2, 0x7632;" : "=r"(d) : "r"(a), "r"(b));
    return d;
}
__device__ __forceinline__ uint32_t bf16x2_rn(float lo_e, float hi_e) {
    uint32_t d;
    asm("cvt.rn.bf16x2.f32 %0, %1, %2;" : "=r"(d) : "f"(hi_e), "f"(lo_e));
    return d;
}
__device__ __forceinline__ void split4(float4 v, uint32_t* hw, uint32_t* lw) {
    uint32_t ux = __float_as_uint(v.x), uy = __float_as_uint(v.y);
    uint32_t uz = __float_as_uint(v.z), uw = __float_as_uint(v.w);
    hw[0] = prmt_hi(ux, uy);
    hw[1] = prmt_hi(uz, uw);
    float lx = v.x - __uint_as_float(ux & 0xFFFF0000u);
    float ly = v.y - __uint_as_float(uy & 0xFFFF0000u);
    float lz = v.z - __uint_as_float(uz & 0xFFFF0000u);
    float lw_ = v.w - __uint_as_float(uw & 0xFFFF0000u);
    lw[0] = bf16x2_rn(lx, ly);
    lw[1] = bf16x2_rn(lz, lw_);
}
__device__ __forceinline__ void mma_bf16(float* d, const uint32_t* a,
                                         const uint32_t* b) {
    asm volatile(
        "mma.sync.aligned.m16n8k16.row.col.f32.bf16.bf16.f32 "
        "{%0,%1,%2,%3}, {%4,%5,%6,%7}, {%8,%9}, {%0,%1,%2,%3};"
        : "+f"(d[0]), "+f"(d[1]), "+f"(d[2]), "+f"(d[3])
        : "r"(a[0]), "r"(a[1]), "r"(a[2]), "r"(a[3]), "r"(b[0]), "r"(b[1]));
}

#define BA_STR 36   // uint32 words per 64-K smem row (32 data + 4 pad)
#define BB_STR 68   // uint32 words per 128-K smem row (64 data + 4 pad)
#define BSM_TOTAL ((2*128*BA_STR + 2*128*BB_STR) * 4)   // 106496 B
#define FSM_TOTAL (4*128*BA_STR * 4)                    // 73728 B

// ============================================================================
// gemm_tc: C[i,j] = sum_k A[i,k]*B[j,k] (+bias), K=128  (R9-best, unchanged)
// ============================================================================
struct TJob {
    const float* A;
    const float* B;
    const float* bias;
    float*       C;
    int ldc;
    int coff;
};
struct TJobs { TJob j[2]; };

__global__ void __launch_bounds__(256, 2) gemm_tc(TJobs jobs, int nrows)
{
    extern __shared__ uint32_t smw[];
    uint32_t* Ah = smw;
    uint32_t* Al = smw + 128 * BA_STR;
    uint32_t* Bh = smw + 2 * 128 * BA_STR;
    uint32_t* Bl = Bh + 128 * BB_STR;

    const TJob job = jobs.j[blockIdx.y];
    const int row0 = blockIdx.x * 128;
    const int tid  = threadIdx.x;
    const int wid  = tid >> 5, lane = tid & 31;
    const int wm   = wid >> 1, wn = wid & 1;
    const int g    = lane >> 2, ti = lane & 3;

#pragma unroll
    for (int i = 0; i < 16; i++) {
        int lin = tid + i * 256;
        int n   = lin >> 5;
        int kq  = (lin & 31) << 2;
        float4 v = *(const float4*)(job.B + (size_t)n * 128 + kq);
        uint32_t hw[2], lw[2];
        split4(v, hw, lw);
        int base = n * BB_STR + (kq >> 1);
        Bh[base] = hw[0]; Bh[base + 1] = hw[1];
        Bl[base] = lw[0]; Bl[base + 1] = lw[1];
    }

    float acc[2][8][4];
#pragma unroll
    for (int mt = 0; mt < 2; mt++)
#pragma unroll
        for (int nt = 0; nt < 8; nt++)
#pragma unroll
            for (int u = 0; u < 4; u++) acc[mt][nt][u] = 0.f;

    for (int c = 0; c < 2; c++) {
#pragma unroll
        for (int i = 0; i < 8; i++) {
            int lin = tid + i * 256;
            int r   = lin >> 4;
            int kq  = (lin & 15) << 2;
            int grow = row0 + r;
            float4 v = make_float4(0.f, 0.f, 0.f, 0.f);
            if (grow < nrows)
                v = *(const float4*)(job.A + (size_t)grow * 128 + c * 64 + kq);
            uint32_t hw[2], lw[2];
            split4(v, hw, lw);
            int base = r * BA_STR + (kq >> 1);
            Ah[base] = hw[0]; Ah[base + 1] = hw[1];
            Al[base] = lw[0]; Al[base + 1] = lw[1];
        }
        __syncthreads();

#pragma unroll
        for (int s = 0; s < 4; s++) {
            const int k0w = s * 8;
            uint32_t ah[2][4], al[2][4];
#pragma unroll
            for (int mt = 0; mt < 2; mt++) {
                int rb = wm * 32 + mt * 16;
                int i0 = (rb + g)     * BA_STR + k0w + ti;
                int i1 = (rb + g + 8) * BA_STR + k0w + ti;
                ah[mt][0] = Ah[i0];
                ah[mt][1] = Ah[i1];
                ah[mt][2] = Ah[i0 + 4];
                ah[mt][3] = Ah[i1 + 4];
                al[mt][0] = Al[i0];
                al[mt][1] = Al[i1];
                al[mt][2] = Al[i0 + 4];
                al[mt][3] = Al[i1 + 4];
            }
#pragma unroll
            for (int nt = 0; nt < 8; nt++) {
                int n = wn * 64 + nt * 8 + g;
                int b0 = n * BB_STR + c * 32 + k0w + ti;
                uint32_t bh[2], bl[2];
                bh[0] = Bh[b0]; bh[1] = Bh[b0 + 4];
                bl[0] = Bl[b0]; bl[1] = Bl[b0 + 4];
#pragma unroll
                for (int mt = 0; mt < 2; mt++) {
                    mma_bf16(acc[mt][nt], ah[mt], bh);
                    mma_bf16(acc[mt][nt], ah[mt], bl);
                    mma_bf16(acc[mt][nt], al[mt], bh);
                }
            }
        }
        __syncthreads();
    }

#pragma unroll
    for (int mt = 0; mt < 2; mt++) {
#pragma unroll
        for (int h = 0; h < 2; h++) {
            int grow = row0 + wm * 32 + mt * 16 + g + h * 8;
            if (grow >= nrows) continue;
            float* cp = job.C + (size_t)grow * job.ldc + job.coff + wn * 64;
#pragma unroll
            for (int nt = 0; nt < 8; nt++) {
                int col = nt * 8 + 2 * ti;
                float vx = acc[mt][nt][2 * h];
                float vy = acc[mt][nt][2 * h + 1];
                if (job.bias) {
                    vx += job.bias[wn * 64 + col];
                    vy += job.bias[wn * 64 + col + 1];
                }
                *(float2*)(cp + col) = make_float2(vx, vy);
            }
        }
    }
}

// ============================================================================
// gemm_fin: out = AGG @ [Wcon|Wdis]^T + g2*xself (+residual), K=256 in 4 chunks
// ============================================================================
__global__ void __launch_bounds__(256, 2) gemm_fin(
    const float* __restrict__ AGG, const float* __restrict__ Wcon,
    const float* __restrict__ Wdis, const float* __restrict__ G,
    const float* __restrict__ G2, const float* __restrict__ residual,
    float* __restrict__ out, int nrows)
{
    extern __shared__ uint32_t smw[];
    uint32_t* Ah = smw;
    uint32_t* Al = smw + 128 * BA_STR;
    uint32_t* Bh = smw + 2 * 128 * BA_STR;
    uint32_t* Bl = smw + 3 * 128 * BA_STR;

    const int row0 = blockIdx.x * 128;
    const int tid  = threadIdx.x;
    const int wid  = tid >> 5, lane = tid & 31;
    const int wm   = wid >> 1, wn = wid & 1;
    const int g    = lane >> 2, ti = lane & 3;

    float acc[2][8][4];
#pragma unroll
    for (int mt = 0; mt < 2; mt++)
#pragma unroll
        for (int nt = 0; nt < 8; nt++)
#pragma unroll
            for (int u = 0; u < 4; u++) acc[mt][nt][u] = 0.f;

    for (int c = 0; c < 4; c++) {
        const float* wsrc = (c < 2) ? Wcon : Wdis;
        const int woff = (c & 1) * 64;
#pragma unroll
        for (int i = 0; i < 8; i++) {
            int lin = tid + i * 256;
            int r   = lin >> 4;
            int kq  = (lin & 15) << 2;
            int grow = row0 + r;
            float4 v = make_float4(0.f, 0.f, 0.f, 0.f);
            if (grow < nrows)
                v = *(const float4*)(AGG + (size_t)grow * 256 + c * 64 + kq);
            uint32_t hw[2], lw[2];
            split4(v, hw, lw);
            int base = r * BA_STR + (kq >> 1);
            Ah[base] = hw[0]; Ah[base + 1] = hw[1];
            Al[base] = lw[0]; Al[base + 1] = lw[1];
        }
#pragma unroll
        for (int i = 0; i < 8; i++) {
            int lin = tid + i * 256;
            int n   = lin >> 4;
            int kq  = (lin & 15) << 2;
            float4 v = *(const float4*)(wsrc + (size_t)n * 128 + woff + kq);
            uint32_t hw[2], lw[2];
            split4(v, hw, lw);
            int base = n * BA_STR + (kq >> 1);
            Bh[base] = hw[0]; Bh[base + 1] = hw[1];
            Bl[base] = lw[0]; Bl[base + 1] = lw[1];
        }
        __syncthreads();

#pragma unroll
        for (int s = 0; s < 4; s++) {
            const int k0w = s * 8;
            uint32_t ah[2][4], al[2][4];
#pragma unroll
            for (int mt = 0; mt < 2; mt++) {
                int rb = wm * 32 + mt * 16;
                int i0 = (rb + g)     * BA_STR + k0w + ti;
                int i1 = (rb + g + 8) * BA_STR + k0w + ti;
                ah[mt][0] = Ah[i0];
                ah[mt][1] = Ah[i1];
                ah[mt][2] = Ah[i0 + 4];
                ah[mt][3] = Ah[i1 + 4];
                al[mt][0] = Al[i0];
                al[mt][1] = Al[i1];
                al[mt][2] = Al[i0 + 4];
                al[mt][3] = Al[i1 + 4];
            }
#pragma unroll
            for (int nt = 0; nt < 8; nt++) {
                int n = wn * 64 + nt * 8 + g;
                int b0 = n * BA_STR + k0w + ti;
                uint32_t bh[2], bl[2];
                bh[0] = Bh[b0]; bh[1] = Bh[b0 + 4];
                bl[0] = Bl[b0]; bl[1] = Bl[b0 + 4];
#pragma unroll
                for (int mt = 0; mt < 2; mt++) {
                    mma_bf16(acc[mt][nt], ah[mt], bh);
                    mma_bf16(acc[mt][nt], ah[mt], bl);
                    mma_bf16(acc[mt][nt], al[mt], bh);
                }
            }
        }
        __syncthreads();
    }

#pragma unroll
    for (int mt = 0; mt < 2; mt++) {
#pragma unroll
        for (int h = 0; h < 2; h++) {
            int grow = row0 + wm * 32 + mt * 16 + g + h * 8;
            if (grow >= nrows) continue;
            float g2v = G2[grow];
            const float* xs = G + (size_t)grow * 256 + 128 + wn * 64;
            const float* rs = residual ? residual + (size_t)grow * 128 + wn * 64
                                       : nullptr;
            float* cp = out + (size_t)grow * 128 + wn * 64;
#pragma unroll
            for (int nt = 0; nt < 8; nt++) {
                int col = nt * 8 + 2 * ti;
                float2 xv = *(const float2*)(xs + col);
                float vx = acc[mt][nt][2 * h]     + g2v * xv.x;
                float vy = acc[mt][nt][2 * h + 1] + g2v * xv.y;
                if (rs) {
                    float2 rv = *(const float2*)(rs + col);
                    vx += rv.x; vy += rv.y;
                }
                *(float2*)(cp + col) = make_float2(vx, vy);
            }
        }
    }
}

// ---------------- fused gate vectors: V[k][j], V[384+k][j] ------------------
__global__ void gatevec_k(const float* __restrict__ Wcon,
                          const float* __restrict__ Wdis,
                          const float* __restrict__ Wgate,
                          float* __restrict__ V)
{
    int b = blockIdx.x;         // 0..5
    int k = b >> 1;
    int half = b & 1;
    int j = threadIdx.x;        // 0..127
    const float* W  = half ? Wdis : Wcon;
    const float* wg = Wgate + k * 384 + half * 128;
    float s = 0.f;
#pragma unroll 8
    for (int i = 0; i < 128; i++)
        s = fmaf(wg[i], W[i * 128 + j], s);
    V[half * 384 + k * 128 + j] = s;
}

// ---------------- scalar GEMM (classifier only, ncols=40) -------------------
struct GemmJob {
    const float* A;
    const float* B;
    const float* bias;
    float*       C;
    int ldc;
    int coff;
    int ncols;
};
struct GemmJobs { GemmJob j[2]; };

__device__ __forceinline__ void fma2(unsigned long long& d,
                                     unsigned long long a, unsigned long long b) {
    asm("fma.rn.f32x2 %0, %1, %2, %0;" : "+l"(d) : "l"(a), "l"(b));
}
__device__ __forceinline__ void unpack2(unsigned long long v, float& lo, float& hi) {
    asm("mov.b64 {%0, %1}, %2;" : "=f"(lo), "=f"(hi) : "l"(v));
}

#define AS_STRIDE 260
#define BS_STRIDE 144

__global__ void __launch_bounds__(256, 2) gemm_nt(
    GemmJobs jobs, int nrows)
{
    const GemmJob job = jobs.j[blockIdx.y];
    const float* __restrict__ A    = job.A;
    const float* __restrict__ B    = job.B;
    const float* __restrict__ bias = job.bias;
    const int ncols = job.ncols;
    const int row0  = blockIdx.x * 128;

    __shared__ float As[16][AS_STRIDE];
    __shared__ float Bs[16][BS_STRIDE];

    const int t  = threadIdx.x;
    const int tx = t & 15;
    const int ty = t >> 4;

    unsigned long long acc[8][4];
#pragma unroll
    for (int y = 0; y < 8; y++)
#pragma unroll
        for (int xp = 0; xp < 4; xp++) acc[y][xp] = 0ULL;

    const int b_base = tx * 8 + ((tx >> 2) << 2);

    for (int k0 = 0; k0 < 128; k0 += 16) {
#pragma unroll
        for (int i = 0; i < 2; i++) {
            int lin = t + i * 256;
            int r   = lin >> 2;
            int kq  = lin & 3;
            float4 v = make_float4(0.f, 0.f, 0.f, 0.f);
            int grow = row0 + r;
            if (grow < nrows)
                v = *(const float4*)(A + (size_t)grow * 128 + k0 + kq * 4);
            *(float2*)&As[kq * 4 + 0][2 * r] = make_float2(v.x, v.x);
            *(float2*)&As[kq * 4 + 1][2 * r] = make_float2(v.y, v.y);
            *(float2*)&As[kq * 4 + 2][2 * r] = make_float2(v.z, v.z);
            *(float2*)&As[kq * 4 + 3][2 * r] = make_float2(v.w, v.w);
        }
#pragma unroll
        for (int i = 0; i < 2; i++) {
            int lin = t + i * 256;
            int j   = lin >> 2;
            int kq  = lin & 3;
            float4 v = make_float4(0.f, 0.f, 0.f, 0.f);
            if (j < ncols)
                v = *(const float4*)(B + (size_t)j * 128 + k0 + kq * 4);
            int pj = j + ((j >> 5) << 2);
            Bs[kq * 4 + 0][pj] = v.x;
            Bs[kq * 4 + 1][pj] = v.y;
            Bs[kq * 4 + 2][pj] = v.z;
            Bs[kq * 4 + 3][pj] = v.w;
        }
        __syncthreads();
#pragma unroll
        for (int kk = 0; kk < 16; kk++) {
            unsigned long long ad[8], bp[4];
            const ulonglong2* ap = (const ulonglong2*)&As[kk][ty * 16];
            const ulonglong2* bq = (const ulonglong2*)&Bs[kk][b_base];
#pragma unroll
            for (int i = 0; i < 4; i++) {
                ulonglong2 u = ap[i];
                ad[2 * i]     = u.x;
                ad[2 * i + 1] = u.y;
            }
#pragma unroll
            for (int i = 0; i < 2; i++) {
                ulonglong2 u = bq[i];
                bp[2 * i]     = u.x;
                bp[2 * i + 1] = u.y;
            }
#pragma unroll
            for (int y = 0; y < 8; y++)
#pragma unroll
                for (int xp = 0; xp < 4; xp++)
                    fma2(acc[y][xp], ad[y], bp[xp]);
        }
        __syncthreads();
    }

#pragma unroll
    for (int y = 0; y < 8; y++) {
        int grow = row0 + ty * 8 + y;
        if (grow >= nrows) continue;
        float* cp = job.C + (size_t)grow * job.ldc + job.coff;
        float c[8];
#pragma unroll
        for (int xp = 0; xp < 4; xp++)
            unpack2(acc[y][xp], c[2 * xp], c[2 * xp + 1]);
#pragma unroll
        for (int xq = 0; xq < 2; xq++) {
            int col = tx * 8 + xq * 4;
            if (col >= ncols) continue;
            float4 v = make_float4(c[xq * 4 + 0], c[xq * 4 + 1],
                                   c[xq * 4 + 2], c[xq * 4 + 3]);
            if (bias) {
                v.x += bias[col + 0];
                v.y += bias[col + 1];
                v.z += bias[col + 2];
                v.w += bias[col + 3];
            }
            *(float4*)(cp + col) = v;
        }
    }
}

// ---------------- BatchNorm --------------------------------------------------
__global__ void bn_stats(const float* __restrict__ X, float* __restrict__ stats)
{
    int c  = threadIdx.x;
    int r0 = blockIdx.x * 64;
    int r1 = min(r0 + 64, N_NODES);
    float s = 0.f, q = 0.f;
    for (int r = r0; r < r1; r++) {
        float v = X[(size_t)r * 128 + c];
        s += v;
        q = fmaf(v, v, q);
    }
    atomicAdd(&stats[c], s);
    atomicAdd(&stats[128 + c], q);
}

__global__ void bn_apply(const float4* __restrict__ X, const float* __restrict__ stats,
                         const float* __restrict__ gamma, const float* __restrict__ beta,
                         const float4* __restrict__ residual, float4* __restrict__ out)
{
    int i = blockIdx.x * blockDim.x + threadIdx.x;
    if (i >= N_NODES * 32) return;
    int c0 = (i & 31) * 4;
    const float invN = 1.f / (float)N_NODES;
    float4 v = X[i];
    float r[4] = {v.x, v.y, v.z, v.w};
#pragma unroll
    for (int k = 0; k < 4; k++) {
        int c = c0 + k;
        float m   = stats[c] * invN;
        float var = stats[128 + c] * invN - m * m;
        float u = gamma[c] * (r[k] - m) * rsqrtf(var + 1e-5f) + beta[c];
        r[k] = fmaxf(u, 0.f);
    }
    float4 o = make_float4(r[0], r[1], r[2], r[3]);
    if (residual) {
        float4 rv = residual[i];
        o.x += rv.x; o.y += rv.y; o.z += rv.z; o.w += rv.w;
    }
    out[i] = o;
}

// ---------------- small utility kernels -------------------------------------
__global__ void zero_f(float* __restrict__ p, int n)
{
    int i = blockIdx.x * blockDim.x + threadIdx.x;
    if (i < n) p[i] = 0.f;
}

__global__ void recip_f(float* __restrict__ p, int n)
{
    int i = blockIdx.x * blockDim.x + threadIdx.x;
    if (i < n) p[i] = 1.f / p[i];
}

__global__ void init_counts_k(int* __restrict__ cnt)
{
    int i = blockIdx.x * blockDim.x + threadIdx.x;
    if (i < N_NODES) cnt[i] = 1;   // self loop
}

__global__ void hist_k(const int* __restrict__ ei1, int* __restrict__ cnt)
{
    int e = blockIdx.x * blockDim.x + threadIdx.x;
    if (e < N_EDGES) atomicAdd(&cnt[ei1[e]], 1);
}

__global__ void scan_k(const int* __restrict__ cnt, int* __restrict__ off,
                       int* __restrict__ cur)
{
    __shared__ int sh[1024];
    const int CH = (N_NODES + 1023) / 1024;
    int t = threadIdx.x;
    int base = t * CH;
    int local = 0;
    for (int i = 0; i < CH; i++) {
        int idx = base + i;
        if (idx < N_NODES) local += cnt[idx];
    }
    sh[t] = local;
    __syncthreads();
    for (int o = 1; o < 1024; o <<= 1) {
        int v = 0;
        if (t >= o) v = sh[t - o];
        __syncthreads();
        if (t >= o) sh[t] += v;
        __syncthreads();
    }
    int run = (t == 0) ? 0 : sh[t - 1];
    for (int i = 0; i < CH; i++) {
        int idx = base + i;
        if (idx < N_NODES) {
            off[idx] = run;
            cur[idx] = run;
            run += cnt[idx];
        }
    }
    if (t == 0) off[N_NODES] = EAUG;
}

__global__ void csr_fill_k(const int* __restrict__ ei1, int* __restrict__ cur,
                           int* __restrict__ eid)
{
    int e = blockIdx.x * blockDim.x + threadIdx.x;
    if (e >= EAUG) return;
    int c = (e < N_EDGES) ? ei1[e] : (e - N_EDGES);
    int pos = atomicAdd(&cur[c], 1);
    eid[pos] = e;
}

// ---------------- per-node dots: p, q (edge score) + t_k (gate-self) --------
// also zeroes Z for the following edge pass.
__global__ void pq_kernel(const float* __restrict__ G, const float* __restrict__ Wh,
                          const float* __restrict__ Wgate,
                          float2* __restrict__ PQ, float4* __restrict__ T,
                          float* __restrict__ Z)
{
    int node = (blockIdx.x * blockDim.x + threadIdx.x) >> 5;
    int lane = threadIdx.x & 31;
    if (node >= N_NODES) return;
    float4 xg = ((const float4*)(G + (size_t)node * 256))[lane];
    float4 xs = ((const float4*)(G + (size_t)node * 256 + 128))[lane];
    float4 a  = ((const float4*)Wh)[lane];
    float4 b  = ((const float4*)Wh)[lane + 32];
    float p = xg.x * a.x + xg.y * a.y + xg.z * a.z + xg.w * a.w;
    float q = xg.x * b.x + xg.y * b.y + xg.z * b.z + xg.w * b.w;
    float t[3];
#pragma unroll
    for (int k = 0; k < 3; k++) {
        float4 w = ((const float4*)(Wgate + k * 384 + 256))[lane];
        t[k] = w.x * xs.x + w.y * xs.y + w.z * xs.z + w.w * xs.w;
    }
#pragma unroll
    for (int o = 16; o > 0; o >>= 1) {
        p += __shfl_xor_sync(0xffffffffu, p, o);
        q += __shfl_xor_sync(0xffffffffu, q, o);
        t[0] += __shfl_xor_sync(0xffffffffu, t[0], o);
        t[1] += __shfl_xor_sync(0xffffffffu, t[1], o);
        t[2] += __shfl_xor_sync(0xffffffffu, t[2], o);
    }
    if (lane == 0) {
        PQ[node] = make_float2(p, q);
        T[node]  = make_float4(t[0], t[1], t[2], 0.f);
        Z[node] = 0.f;
        Z[N_NODES + node] = 0.f;
    }
}

// ---------------- edge pass 1 (unchanged from R9) ----------------------------
__global__ void edge_pass1(const float* __restrict__ G,
                           const int* __restrict__ ei0, const int* __restrict__ ei1,
                           const float2* __restrict__ PQ, const float* __restrict__ bh,
                           float2* __restrict__ s_buf, float* __restrict__ Z)
{
    int gw   = (blockIdx.x * blockDim.x + threadIdx.x) >> 5;
    int lane = threadIdx.x & 31;
    if (gw >= EAUG) return;
    int r, c;
    if (gw < N_EDGES) { r = ei0[gw]; c = ei1[gw]; }
    else              { r = gw - N_EDGES; c = r; }

    float4 xr = ((const float4*)(G + (size_t)r * 256))[lane];
    float4 xc = ((const float4*)(G + (size_t)c * 256))[lane];

    float dx = xr.x - xc.x, dy = xr.y - xc.y, dz = xr.z - xc.z, dw = xr.w - xc.w;
    float ss = dx * dx + dy * dy + dz * dz + dw * dw;
#pragma unroll
    for (int o = 16; o > 0; o >>= 1)
        ss += __shfl_xor_sync(0xffffffffu, ss, o);
    if (lane == 0) {
        float g = sqrtf(ss + 1e-12f);
        float t = PQ[r].x + PQ[c].y + bh[0];
        float h = fmaxf(t, 0.f) + log1pf(__expf(-fabsf(t)));   // softplus
        float s = 1.f / (1.f + __expf(g + h));                 // sigmoid(-(g+h))
        float es = __expf(s);
        float ed = __expf(1.f - s);
        s_buf[gw] = make_float2(es, ed);
        atomicAdd(&Z[r],           es);
        atomicAdd(&Z[N_NODES + r], ed);
    }
}

// ---------------- aggregation + fused gate softmax ---------------------------
// Writes AGG = [g0*sc | g1*sd] and g2 per node.
__global__ void agg_k(const float* __restrict__ X,
                      const int* __restrict__ off, const int* __restrict__ eid,
                      const int* __restrict__ ei0,
                      const float2* __restrict__ s_buf, const float* __restrict__ invZ,
                      const float* __restrict__ V, const float4* __restrict__ T,
                      const float* __restrict__ bgate,
                      float* __restrict__ AGG, float* __restrict__ G2)
{
    int node = (blockIdx.x * blockDim.x + threadIdx.x) >> 5;
    int lane = threadIdx.x & 31;
    if (node >= N_NODES) return;

    int p0 = off[node], p1 = off[node + 1];
    float4 ac = make_float4(0.f, 0.f, 0.f, 0.f);
    float4 ad = make_float4(0.f, 0.f, 0.f, 0.f);
    for (int p = p0; p < p1; p++) {
        int e = eid[p];
        int r = (e < N_EDGES) ? ei0[e] : (e - N_EDGES);
        float2 es = s_buf[e];
        float wc = es.x * invZ[r];
        float wd = es.y * invZ[N_NODES + r];
        float4 v = ((const float4*)(X + (size_t)r * 128))[lane];
        ac.x = fmaf(wc, v.x, ac.x); ac.y = fmaf(wc, v.y, ac.y);
        ac.z = fmaf(wc, v.z, ac.z); ac.w = fmaf(wc, v.w, ac.w);
        ad.x = fmaf(wd, v.x, ad.x); ad.y = fmaf(wd, v.y, ad.y);
        ad.z = fmaf(wd, v.z, ad.z); ad.w = fmaf(wd, v.w, ad.w);
    }

    // gate logits from fused vectors
    float l[3];
#pragma unroll
    for (int k = 0; k < 3; k++) {
        float4 v0 = ((const float4*)(V + k * 128))[lane];
        float4 v1 = ((const float4*)(V + 384 + k * 128))[lane];
        l[k] = v0.x * ac.x + v0.y * ac.y + v0.z * ac.z + v0.w * ac.w
             + v1.x * ad.x + v1.y * ad.y + v1.z * ad.z + v1.w * ad.w;
    }
#pragma unroll
    for (int o = 16; o > 0; o >>= 1) {
        l[0] += __shfl_xor_sync(0xffffffffu, l[0], o);
        l[1] += __shfl_xor_sync(0xffffffffu, l[1], o);
        l[2] += __shfl_xor_sync(0xffffffffu, l[2], o);
    }
    float4 tt = T[node];
    l[0] += tt.x + bgate[0];
    l[1] += tt.y + bgate[1];
    l[2] += tt.z + bgate[2];
    float m  = fmaxf(l[0], fmaxf(l[1], l[2]));
    float e0 = __expf(l[0] - m), e1 = __expf(l[1] - m), e2 = __expf(l[2] - m);
    float inv = 1.f / (e0 + e1 + e2);
    float g0 = e0 * inv, g1 = e1 * inv, g2 = e2 * inv;

    float4 oc = make_float4(g0 * ac.x, g0 * ac.y, g0 * ac.z, g0 * ac.w);
    float4 od = make_float4(g1 * ad.x, g1 * ad.y, g1 * ad.z, g1 * ad.w);
    ((float4*)(AGG + (size_t)node * 256))[lane]       = oc;
    ((float4*)(AGG + (size_t)node * 256 + 128))[lane] = od;
    if (lane == 0) G2[node] = g2;
}

// ---------------- launch ------------------------------------------------------
extern "C" void kernel_launch(void* const* d_in, const int* in_sizes, int n_in,
                              void* d_out, int out_size)
{
    (void)in_sizes; (void)n_in; (void)out_size;
    const float* x       = (const float*)d_in[0];
    const int*   ei      = (const int*)d_in[1];
    const float* mlp_W   = (const float*)d_in[2];
    const float* mlp_b   = (const float*)d_in[3];
    const float* mlp_g   = (const float*)d_in[4];
    const float* mlp_be  = (const float*)d_in[5];
    const float* bn0_g   = (const float*)d_in[6];
    const float* bn0_be  = (const float*)d_in[7];
    const float* cls_W   = (const float*)d_in[8];
    const float* cls_b   = (const float*)d_in[9];
    const float* Wg[2]    = {(const float*)d_in[10], (const float*)d_in[19]};
    const float* Wh[2]    = {(const float*)d_in[11], (const float*)d_in[20]};
    const float* bh[2]    = {(const float*)d_in[12], (const float*)d_in[21]};
    const float* Wcon[2]  = {(const float*)d_in[13], (const float*)d_in[22]};
    const float* Wdis[2]  = {(const float*)d_in[14], (const float*)d_in[23]};
    const float* Wself[2] = {(const float*)d_in[15], (const float*)d_in[24]};
    const float* bself[2] = {(const float*)d_in[16], (const float*)d_in[25]};
    const float* Wgate[2] = {(const float*)d_in[17], (const float*)d_in[26]};
    const float* bgate[2] = {(const float*)d_in[18], (const float*)d_in[27]};
    const int* ei0 = ei;
    const int* ei1 = ei + N_EDGES;
    float* out = (float*)d_out;

    float *pH0, *pX1, *pTmp, *pG, *pAGG, *pG2, *pZ, *pStats, *pV;
    float2 *pS, *pPQ;
    float4 *pT;
    int *pOff, *pCur, *pCnt, *pEid;
    cudaGetSymbolAddress((void**)&pH0,   d_h0);
    cudaGetSymbolAddress((void**)&pX1,   d_x1);
    cudaGetSymbolAddress((void**)&pTmp,  d_tmp);
    cudaGetSymbolAddress((void**)&pG,    d_G);
    cudaGetSymbolAddress((void**)&pAGG,  d_AGG);
    cudaGetSymbolAddress((void**)&pG2,   d_g2);
    cudaGetSymbolAddress((void**)&pPQ,   d_PQ);
    cudaGetSymbolAddress((void**)&pT,    d_T);
    cudaGetSymbolAddress((void**)&pV,    d_V);
    cudaGetSymbolAddress((void**)&pS,    d_s);
    cudaGetSymbolAddress((void**)&pZ,    d_Z);
    cudaGetSymbolAddress((void**)&pStats,d_stats);
    cudaGetSymbolAddress((void**)&pOff,  d_off);
    cudaGetSymbolAddress((void**)&pCur,  d_cur);
    cudaGetSymbolAddress((void**)&pCnt,  d_cnt);
    cudaGetSymbolAddress((void**)&pEid,  d_eid);

    cudaFuncSetAttribute(gemm_tc, cudaFuncAttributeMaxDynamicSharedMemorySize,
                         BSM_TOTAL);
    cudaFuncSetAttribute(gemm_fin, cudaFuncAttributeMaxDynamicSharedMemorySize,
                         FSM_TOTAL);

    const int GR = (N_NODES + 127) / 128;          // 391 row blocks
    const int NODE_WARPS = (N_NODES * 32 + 255) / 256;

    // ---- MLP + BN + relu -> h0
    {
        TJobs tj = {};
        tj.j[0] = {x, mlp_W, mlp_b, pTmp, 128, 0};
        tj.j[1] = tj.j[0];
        gemm_tc<<<dim3(GR, 1), 256, BSM_TOTAL>>>(tj, N_NODES);
    }
    zero_f<<<1, 256>>>(pStats, 256);
    bn_stats<<<(N_NODES + 63) / 64, 128>>>(pTmp, pStats);
    bn_apply<<<NODE_WARPS, 256>>>((const float4*)pTmp, pStats,
                                  mlp_g, mlp_be, nullptr, (float4*)pH0);

    // ---- CSR by col (shared by both layers)
    init_counts_k<<<(N_NODES + 255) / 256, 256>>>(pCnt);
    hist_k<<<(N_EDGES + 255) / 256, 256>>>(ei1, pCnt);
    scan_k<<<1, 1024>>>(pCnt, pOff, pCur);
    csr_fill_k<<<(EAUG + 255) / 256, 256>>>(ei1, pCur, pEid);

    // ---- conv layers
    const float* lin[2] = {pH0, pX1};
    for (int l = 0; l < 2; l++) {
        const float* X = lin[l];
        gatevec_k<<<6, 128>>>(Wcon[l], Wdis[l], Wgate[l], pV);
        {   // G = [X@Wg.T | X@Wself.T + bself]
            TJobs tj = {};
            tj.j[0] = {X, Wg[l],    nullptr,  pG, 256, 0};
            tj.j[1] = {X, Wself[l], bself[l], pG, 256, 128};
            gemm_tc<<<dim3(GR, 2), 256, BSM_TOTAL>>>(tj, N_NODES);
        }
        pq_kernel<<<NODE_WARPS, 256>>>(pG, Wh[l], Wgate[l], pPQ, pT, pZ);
        edge_pass1<<<(EAUG * 32 + 255) / 256, 256>>>(pG, ei0, ei1, pPQ, bh[l],
                                                     pS, pZ);
        recip_f<<<(2 * N_NODES + 255) / 256, 256>>>(pZ, 2 * N_NODES);
        agg_k<<<NODE_WARPS, 256>>>(X, pOff, pEid, ei0, pS, pZ, pV, pT,
                                   bgate[l], pAGG, pG2);
        gemm_fin<<<GR, 256, FSM_TOTAL>>>(pAGG, Wcon[l], Wdis[l], pG, pG2,
                                         (l == 0) ? nullptr : pX1, pTmp,
                                         N_NODES);
        if (l == 0) {
            zero_f<<<1, 256>>>(pStats, 256);
            bn_stats<<<(N_NODES + 63) / 64, 128>>>(pTmp, pStats);
            bn_apply<<<NODE_WARPS, 256>>>((const float4*)pTmp, pStats,
                                          bn0_g, bn0_be,
                                          (const float4*)pH0, (float4*)pX1);
        }
    }

    // ---- classifier: out = x2 @ cls_W.T + cls_b   (x2 lives in d_tmp)
    {
        GemmJobs gj = {};
        gj.j[0] = {pTmp, cls_W, cls_b, out, 40, 0, 40};
        gj.j[1] = gj.j[0];
        gemm_nt<<<dim3(GR, 1), 256>>>(gj, N_NODES);
    }
}